// round 12
// baseline (speedup 1.0000x reference)
#include <cuda_runtime.h>
#include <cuda_bf16.h>
#include <math.h>
#include <stdint.h>

#define Dd 1024
#define Mm 8192
#define Hh 16
#define Bb 64

typedef __nv_bfloat16 bf16;

// ---------------- scratch (device globals) ----------------------------------
// all bf16 split buffers use [h|l] layout: row r holds hi plane then lo plane.
#define DA __device__ __align__(16)
DA bf16 s_WkT[Dd * 2 * Dd];
DA bf16 s_WvT[Dd * 2 * Dd];
DA bf16 s_Wik[Dd * 2 * Dd];
DA bf16 s_Wiv[Dd * 2 * Dd];
DA bf16 s_Wck[Dd * 2 * Dd];
DA bf16 s_Wcv[Dd * 2 * Dd];
DA bf16 s_keys[Mm * 2 * Dd];
DA bf16 s_vals[Mm * 2 * Dd];
DA bf16 s_kh[Mm * 2 * Dd];          // head-blocked: per row, head h at h*128, [h(64)|l(64)]
DA bf16 s_vhT[Dd * 2 * Mm];         // row n: [h(Mm)|l(Mm)]
DA bf16 s_attn[Bb * Hh * 2 * Mm];
DA bf16 s_x[Bb * 2 * Dd];
DA bf16 s_Wq[Dd * 2 * Dd];
DA bf16 s_q[Bb * 2 * Dd];
DA bf16 s_Wiq[Dd * 2 * Dd];
DA bf16 s_qh[Bb * 2 * Dd];          // head-blocked
DA bf16 s_ctx[Bb * 2 * Dd];
DA bf16 s_outw[Dd * 2 * Dd];
DA bf16 s_gin[Bb * 4 * Dd];
DA bf16 s_gW1[Dd * 4 * Dd];
DA bf16 s_g1[Bb * 2 * Dd];
DA bf16 s_gW2[Dd * 2 * Dd];
DA bf16 s_comb[Bb * 4 * Dd];
DA bf16 s_iW1[2 * Dd * 4 * Dd];
DA bf16 s_i1[Bb * 4 * Dd];
DA bf16 s_iW2[Dd * 4 * Dd];

DA float f_vh[Mm * Dd];
DA float f_scores[Bb * Hh * Mm];
DA float f_q[Bb * Dd];
DA float f_qh[Bb * Dd];
DA float f_ctx[Bb * Dd];
DA float f_ms[Bb * Dd];
DA float f_g1[Bb * Dd];
DA float f_gated[Bb * Dd];
DA float f_i1[Bb * 2 * Dd];
DA float f_bck[Dd];
DA float f_bcv[Dd];

// ---------------- helpers ----------------------------------------------------
__device__ __forceinline__ uint32_t sptr(const void* p)
{
    return (uint32_t)__cvta_generic_to_shared(p);
}

__device__ __forceinline__ void cpasync16(const bf16* g, uint32_t s)
{
    asm volatile("cp.async.ca.shared.global [%0], [%1], 16;" :: "r"(s), "l"(g));
}

__device__ __forceinline__ void ldm4(uint32_t s, uint32_t& r0, uint32_t& r1,
                                     uint32_t& r2, uint32_t& r3)
{
    asm volatile("ldmatrix.sync.aligned.m8n8.x4.shared.b16 {%0,%1,%2,%3}, [%4];"
                 : "=r"(r0), "=r"(r1), "=r"(r2), "=r"(r3) : "r"(s));
}

__device__ __forceinline__ void mma16816(float* c, const uint32_t* a, const uint32_t* b)
{
    asm volatile(
        "mma.sync.aligned.m16n8k16.row.col.f32.bf16.bf16.f32 "
        "{%0,%1,%2,%3}, {%4,%5,%6,%7}, {%8,%9}, {%0,%1,%2,%3};"
        : "+f"(c[0]), "+f"(c[1]), "+f"(c[2]), "+f"(c[3])
        : "r"(a[0]), "r"(a[1]), "r"(a[2]), "r"(a[3]), "r"(b[0]), "r"(b[1]));
}

// write [h|l] split of v.  smode 0: plain (row width 2*ldc, l at +ldc)
// smode 1: head-blocked (head = cc>>6 at hd*128, l at +64); row width 2*ldc
__device__ __forceinline__ void write_split(bf16* sout, long rr, int cc, int ldc,
                                            int smode, float v)
{
    bf16 h = __float2bfloat16(v);
    bf16 l = __float2bfloat16(v - __bfloat162float(h));
    long rb = rr * 2 * (long)ldc;
    if (smode == 0) {
        sout[rb + cc] = h; sout[rb + ldc + cc] = l;
    } else {
        int hd = cc >> 6, j = cc & 63;
        long base = rb + hd * 128 + j;
        sout[base] = h; sout[base + 64] = l;
    }
}

// ---------------- bf16-split HMMA GEMM (TN), phase-tripled ---------------------
// C = Ah*Bh + Ah*Bl + Al*Bh over base depth K1; A,B rows are [h|l] (lo at +K1).
// Warp tile = TMW x TNW; CTA = (BM/TMW)*(BN/TNW) warps = NTH threads.
// Epilogue: v = alpha*acc (+bias) -> act -> (*mul); fp32 C and/or split sout.
// Batched via blockIdx.z = batch*nsplit + split; split-K accumulates atomically.
template <int BM, int BN, int TMW, int TNW, int NTH, bool ATOMIC>
__global__ void __launch_bounds__(NTH) mma_gemm(
    const bf16* __restrict__ A, const bf16* __restrict__ B, float* __restrict__ C,
    int K1, int lda, int ldb, int ldc,
    long sA, long sB, long sC, int nsplit, float alpha,
    const float* __restrict__ bias, int act, const float* __restrict__ mul,
    bf16* __restrict__ sout, int smode)
{
    constexpr int BK = 32, SK = 40;
    constexpr int WMn = BM / TMW;
    constexpr int WNn = BN / TNW;
    static_assert(WMn * WNn * 32 == NTH, "warp layout");
    constexpr int MI = TMW / 16, NI = TNW / 8;
    static_assert((NI & 1) == 0, "NI even");
    constexpr int CA = BM * 4 / NTH;
    constexpr int CB = BN * 4 / NTH;

    extern __shared__ bf16 dsm[];
    bf16* As = dsm;                       // [3][BM*SK]
    bf16* Bs = dsm + 3 * BM * SK;         // [3][BN*SK]

    const int tid = threadIdx.x;
    const int lane = tid & 31;
    const int warp = tid >> 5;
    const int wm = (warp % WMn) * TMW;
    const int wn = (warp / WMn) * TNW;

    const long z = blockIdx.z;
    const long batch = z / nsplit;
    const int split = (int)(z % nsplit);
    A += batch * sA;
    B += batch * sB;
    C += batch * sC;

    const int NTP = K1 / BK;          // tiles per phase
    const int NT = 3 * NTP;           // total tiles
    const int TPS = NT / nsplit;      // tiles handled by this split
    const int t0 = split * TPS;
    const int m0 = blockIdx.y * BM;
    const int n0 = blockIdx.x * BN;

    float acc[MI][NI][4];
#pragma unroll
    for (int i = 0; i < MI; i++)
#pragma unroll
        for (int j = 0; j < NI; j++)
#pragma unroll
            for (int q = 0; q < 4; q++) acc[i][j][q] = 0.0f;

    auto loadT = [&](int buf, int t) {
        const int p = t / NTP;
        const int ktp = t - p * NTP;
        const int Acol = ktp * BK + (p == 2 ? K1 : 0);
        const int Bcol = ktp * BK + (p == 1 ? K1 : 0);
        bf16* Abuf = As + buf * BM * SK;
        bf16* Bbuf = Bs + buf * BN * SK;
#pragma unroll
        for (int i = 0; i < CA; i++) {
            int cid = tid + i * NTH;
            int r = cid >> 2, c = (cid & 3) * 8;
            cpasync16(A + (long)(m0 + r) * lda + Acol + c, sptr(&Abuf[r * SK + c]));
        }
#pragma unroll
        for (int i = 0; i < CB; i++) {
            int cid = tid + i * NTH;
            int r = cid >> 2, c = (cid & 3) * 8;
            cpasync16(B + (long)(n0 + r) * ldb + Bcol + c, sptr(&Bbuf[r * SK + c]));
        }
        asm volatile("cp.async.commit_group;");
    };

    loadT(0, t0);
    loadT(1, t0 + 1);

    for (int i = 0; i < TPS; i++) {
        const int s = i % 3;
        if (i + 1 < TPS) asm volatile("cp.async.wait_group 1;");
        else             asm volatile("cp.async.wait_group 0;");
        __syncthreads();
        if (i + 2 < TPS) loadT((i + 2) % 3, t0 + i + 2);

        bf16* Abuf = As + s * BM * SK;
        bf16* Bbuf = Bs + s * BN * SK;
#pragma unroll
        for (int ki = 0; ki < 2; ki++) {
            uint32_t a[MI][4], b[NI][2];
#pragma unroll
            for (int mi = 0; mi < MI; mi++) {
                int row = wm + mi * 16 + (lane & 15);
                int col = ki * 16 + (lane >> 4) * 8;
                ldm4(sptr(&Abuf[row * SK + col]),
                     a[mi][0], a[mi][1], a[mi][2], a[mi][3]);
            }
#pragma unroll
            for (int nj = 0; nj < NI; nj += 2) {
                int row = wn + nj * 8 + (lane & 15);
                int col = ki * 16 + (lane >> 4) * 8;
                uint32_t r0, r1, r2, r3;
                ldm4(sptr(&Bbuf[row * SK + col]), r0, r1, r2, r3);
                b[nj][0] = r0;     b[nj][1] = r2;
                b[nj + 1][0] = r1; b[nj + 1][1] = r3;
            }
#pragma unroll
            for (int mi = 0; mi < MI; mi++)
#pragma unroll
                for (int nj = 0; nj < NI; nj++)
                    mma16816(acc[mi][nj], a[mi], b[nj]);
        }
    }

    // ---- epilogue
#pragma unroll
    for (int mi = 0; mi < MI; mi++) {
#pragma unroll
        for (int nj = 0; nj < NI; nj++) {
            const int r = m0 + wm + mi * 16 + (lane >> 2);
            const int c = n0 + wn + nj * 8 + (lane & 3) * 2;
#pragma unroll
            for (int q = 0; q < 4; q++) {
                const int rr = r + (q >> 1) * 8;
                const int cc = c + (q & 1);
                float v = acc[mi][nj][q] * alpha;
                if (ATOMIC) {
                    atomicAdd(&C[(long)rr * ldc + cc], v);
                } else {
                    if (bias) v += __ldg(&bias[cc]);
                    if (act == 1) v = fmaxf(v, 0.0f);
                    else if (act == 2) v = 1.0f / (1.0f + expf(-v));
                    if (mul) v *= mul[(long)rr * ldc + cc];
                    if (C) C[(long)rr * ldc + cc] = v;
                    if (sout) write_split(sout, rr, cc, ldc, smode, v);
                }
            }
        }
    }
}

// ---------------- finalize (after atomic split-K) -----------------------------
__global__ void fin_k(const float* __restrict__ acc, float* __restrict__ fout,
                      bf16* __restrict__ sout, long n, int Kc,
                      const float* __restrict__ bias, int act,
                      const float* __restrict__ mul, int smode)
{
    long i = (long)blockIdx.x * 256 + threadIdx.x;
    if (i >= n) return;
    long r = i / Kc;
    int c = (int)(i % Kc);
    float v = acc[i];
    if (bias) v += bias[c];
    if (act == 1) v = fmaxf(v, 0.0f);
    else if (act == 2) v = 1.0f / (1.0f + expf(-v));
    if (mul) v *= mul[i];
    if (fout) fout[i] = v;
    if (sout) write_split(sout, r, c, Kc, smode, v);
}

// ---------------- conversion kernels -----------------------------------------
// [h|l] split, vectorized 4-wide: in R x K fp32 (ldin) -> out R x 2K bf16
__global__ void split2_k(const float* __restrict__ in, bf16* __restrict__ out,
                         int R, int K, int ldin)
{
    long g = (long)blockIdx.x * 256 + threadIdx.x;   // group of 4
    if (g >= (long)R * K / 4) return;
    long i = g * 4;
    int r = (int)(i / K), k = (int)(i % K);
    float4 xv = *(const float4*)&in[(long)r * ldin + k];
    float xs[4] = {xv.x, xv.y, xv.z, xv.w};
    bf16 hs[4], ls[4];
#pragma unroll
    for (int j = 0; j < 4; j++) {
        hs[j] = __float2bfloat16(xs[j]);
        ls[j] = __float2bfloat16(xs[j] - __bfloat162float(hs[j]));
    }
    bf16* o = out + (long)r * 2 * K;
    *(uint2*)&o[k] = *(uint2*)hs;
    *(uint2*)&o[K + k] = *(uint2*)ls;
}

// transpose + [h|l] split: in Kr x Nc fp32 -> out Nc x 2Kr bf16
__global__ void tsplit2_k(const float* __restrict__ in, bf16* __restrict__ out,
                          int Kr, int Nc)
{
    __shared__ float t[32][33];
    int k0 = blockIdx.x * 32, n0 = blockIdx.y * 32;
    int tx = threadIdx.x, ty = threadIdx.y;
#pragma unroll
    for (int i = 0; i < 32; i += 8)
        t[ty + i][tx] = in[(long)(k0 + ty + i) * Nc + n0 + tx];
    __syncthreads();
#pragma unroll
    for (int i = 0; i < 32; i += 8) {
        int n = n0 + ty + i, k = k0 + tx;
        float x = t[tx][ty + i];
        bf16 h = __float2bfloat16(x);
        bf16 l = __float2bfloat16(x - __bfloat162float(h));
        bf16* o = out + (long)n * 2 * Kr + k;
        o[0] = h; o[Kr] = l;
    }
}

// concat + [h|l] split: row = [a|b] (each Dd), out width 4*Dd
__global__ void concat_split2_k(const float* __restrict__ a, const float* __restrict__ b,
                                bf16* __restrict__ o)
{
    int i = blockIdx.x * 256 + threadIdx.x;
    if (i >= Bb * 2 * Dd) return;
    int r = i / (2 * Dd), c = i % (2 * Dd);
    float x = (c < Dd) ? a[r * Dd + c] : b[r * Dd + c - Dd];
    bf16 h = __float2bfloat16(x);
    bf16 l = __float2bfloat16(x - __bfloat162float(h));
    bf16* ro = o + (long)r * 4 * Dd;
    ro[c] = h; ro[2 * Dd + c] = l;
}

// ---------------- misc kernels (fp32) ----------------------------------------
__global__ void bias_combine_k(const float* __restrict__ W, const float* __restrict__ b1,
                               const float* __restrict__ b2, float* __restrict__ out)
{
    const int row = blockIdx.x * blockDim.y + threadIdx.y;
    const int lane = threadIdx.x;
    float s = 0.0f;
    for (int c = lane; c < Dd; c += 32) s += W[row * Dd + c] * b1[c];
#pragma unroll
    for (int o = 16; o; o >>= 1) s += __shfl_down_sync(0xffffffffu, s, o);
    if (lane == 0) out[row] = s + b2[row];
}

__global__ void zero_k(float* p, long n)
{
    long i = (long)blockIdx.x * 256 + threadIdx.x;
    if (i < n) p[i] = 0.0f;
}

// softmax over rows of length Mm (register-cached, input untouched) with fused
// [h|l] split out (row width 2*Mm)
__global__ void softmax_split2_k(const float* __restrict__ s, bf16* __restrict__ sout)
{
    const float* row = s + (size_t)blockIdx.x * Mm;
    bf16* ob = sout + (size_t)blockIdx.x * 2 * Mm;
    __shared__ float red[256];
    const int t = threadIdx.x;
    float v[Mm / 256];
    float mx = -1e30f;
#pragma unroll
    for (int j = 0; j < Mm / 256; j++) {
        v[j] = row[t + j * 256];
        mx = fmaxf(mx, v[j]);
    }
    red[t] = mx;
    __syncthreads();
    for (int o = 128; o; o >>= 1) { if (t < o) red[t] = fmaxf(red[t], red[t + o]); __syncthreads(); }
    mx = red[0];
    __syncthreads();
    float sum = 0.0f;
#pragma unroll
    for (int j = 0; j < Mm / 256; j++) { v[j] = expf(v[j] - mx); sum += v[j]; }
    red[t] = sum;
    __syncthreads();
    for (int o = 128; o; o >>= 1) { if (t < o) red[t] += red[t + o]; __syncthreads(); }
    const float inv = 1.0f / red[0];
#pragma unroll
    for (int j = 0; j < Mm / 256; j++) {
        float w = v[j] * inv;
        bf16 h = __float2bfloat16(w);
        bf16 l = __float2bfloat16(w - __bfloat162float(h));
        ob[t + j * 256] = h;
        ob[Mm + t + j * 256] = l;
    }
}

// ---------------- launch ------------------------------------------------------
#define SYM(v, g) cudaGetSymbolAddress((void**)&v, g)
#define GRD(n) dim3((unsigned)(((long)(n) + 255) / 256))
#define SMEMB(BM, BN) (3 * ((BM) + (BN)) * 40 * (int)sizeof(bf16))

extern "C" void kernel_launch(void* const* d_in, const int* in_sizes, int n_in,
                              void* d_out, int out_size)
{
    (void)in_sizes; (void)n_in; (void)out_size;
    const float* x    = (const float*)d_in[0];
    const float* mk   = (const float*)d_in[1];
    const float* mv   = (const float*)d_in[2];
    const float* Wq   = (const float*)d_in[3];
    const float* bq   = (const float*)d_in[4];
    const float* Wk   = (const float*)d_in[5];
    const float* bk   = (const float*)d_in[6];
    const float* Wv   = (const float*)d_in[7];
    const float* bv   = (const float*)d_in[8];
    const float* ipw  = (const float*)d_in[9];
    const float* ipb  = (const float*)d_in[10];
    const float* outw = (const float*)d_in[11];
    const float* outb = (const float*)d_in[12];
    const float* gW1  = (const float*)d_in[13];
    const float* gb1  = (const float*)d_in[14];
    const float* gW2  = (const float*)d_in[15];
    const float* gb2  = (const float*)d_in[16];
    const float* iW1  = (const float*)d_in[17];
    const float* ib1  = (const float*)d_in[18];
    const float* iW2  = (const float*)d_in[19];
    const float* ib2  = (const float*)d_in[20];
    float* out = (float*)d_out;

    const float* Wiq = ipw;
    const float* Wik = ipw + Dd * Dd;
    const float* Wiv = ipw + 2 * Dd * Dd;
    const float* biq = ipb;
    const float* bik = ipb + Dd;
    const float* biv = ipb + 2 * Dd;

    bf16 *pWkT, *pWvT, *pWik, *pWiv, *pWck, *pWcv, *pkeys, *pvals, *pkh, *pvhT, *pattn;
    bf16 *px, *pWq, *pq, *pWiq, *pqh, *pctx, *poutw, *pgin, *pgW1, *pg1, *pgW2;
    bf16 *pcomb, *piW1, *pi1, *piW2;
    float *fvh, *fsc, *fq, *fqh, *fctx, *fms, *fg1, *fgated, *fi1, *fbck, *fbcv;

    SYM(pWkT, s_WkT); SYM(pWvT, s_WvT); SYM(pWik, s_Wik); SYM(pWiv, s_Wiv);
    SYM(pWck, s_Wck); SYM(pWcv, s_Wcv); SYM(pkeys, s_keys); SYM(pvals, s_vals);
    SYM(pkh, s_kh); SYM(pvhT, s_vhT); SYM(pattn, s_attn);
    SYM(px, s_x); SYM(pWq, s_Wq); SYM(pq, s_q); SYM(pWiq, s_Wiq); SYM(pqh, s_qh);
    SYM(pctx, s_ctx); SYM(poutw, s_outw); SYM(pgin, s_gin); SYM(pgW1, s_gW1);
    SYM(pg1, s_g1); SYM(pgW2, s_gW2); SYM(pcomb, s_comb); SYM(piW1, s_iW1);
    SYM(pi1, s_i1); SYM(piW2, s_iW2);
    SYM(fvh, f_vh); SYM(fsc, f_scores); SYM(fq, f_q); SYM(fqh, f_qh);
    SYM(fctx, f_ctx); SYM(fms, f_ms); SYM(fg1, f_g1); SYM(fgated, f_gated);
    SYM(fi1, f_i1); SYM(fbck, f_bck); SYM(fbcv, f_bcv);

    cudaFuncSetAttribute((const void*)mma_gemm<128, 128, 64, 64, 128, false>,
                         cudaFuncAttributeMaxDynamicSharedMemorySize, SMEMB(128, 128));
    cudaFuncSetAttribute((const void*)mma_gemm<64, 128, 32, 32, 256, true>,
                         cudaFuncAttributeMaxDynamicSharedMemorySize, SMEMB(64, 128));
    cudaFuncSetAttribute((const void*)mma_gemm<64, 128, 32, 32, 256, false>,
                         cudaFuncAttributeMaxDynamicSharedMemorySize, SMEMB(64, 128));
    cudaFuncSetAttribute((const void*)mma_gemm<64, 64, 32, 16, 256, true>,
                         cudaFuncAttributeMaxDynamicSharedMemorySize, SMEMB(64, 64));

    const dim3 blk(256);
    const dim3 blk128(128);
    const dim3 tb(32, 8);

    // --- weight combines: Wck = Wik @ Wk, Wcv = Wiv @ Wv (fused [h|l] out) ------
    tsplit2_k<<<dim3(Dd / 32, Dd / 32), tb>>>(Wk, pWkT, Dd, Dd);
    split2_k<<<GRD(Dd * Dd / 4), blk>>>(Wik, pWik, Dd, Dd, Dd);
    mma_gemm<128, 128, 64, 64, 128, false><<<dim3(8, 8, 1), blk128, SMEMB(128, 128)>>>(
        pWik, pWkT, nullptr, Dd, 2 * Dd, 2 * Dd, Dd, 0, 0, 0, 1, 1.0f,
        nullptr, 0, nullptr, pWck, 0);
    tsplit2_k<<<dim3(Dd / 32, Dd / 32), tb>>>(Wv, pWvT, Dd, Dd);
    split2_k<<<GRD(Dd * Dd / 4), blk>>>(Wiv, pWiv, Dd, Dd, Dd);
    mma_gemm<128, 128, 64, 64, 128, false><<<dim3(8, 8, 1), blk128, SMEMB(128, 128)>>>(
        pWiv, pWvT, nullptr, Dd, 2 * Dd, 2 * Dd, Dd, 0, 0, 0, 1, 1.0f,
        nullptr, 0, nullptr, pWcv, 0);
    bias_combine_k<<<Dd / 8, tb>>>(Wik, bk, bik, fbck);
    bias_combine_k<<<Dd / 8, tb>>>(Wiv, bv, biv, fbcv);

    // --- big GEMMs: kh (fused head split), vh (fp32 + transpose split) ----------
    split2_k<<<GRD((long)Mm * Dd / 4), blk>>>(mk, pkeys, Mm, Dd, Dd);
    split2_k<<<GRD((long)Mm * Dd / 4), blk>>>(mv, pvals, Mm, Dd, Dd);
    mma_gemm<128, 128, 64, 64, 128, false><<<dim3(8, 64, 1), blk128, SMEMB(128, 128)>>>(
        pkeys, pWck, nullptr, Dd, 2 * Dd, 2 * Dd, Dd, 0, 0, 0, 1, 1.0f,
        fbck, 0, nullptr, pkh, 1);
    mma_gemm<128, 128, 64, 64, 128, false><<<dim3(8, 64, 1), blk128, SMEMB(128, 128)>>>(
        pvals, pWcv, fvh, Dd, 2 * Dd, 2 * Dd, Dd, 0, 0, 0, 1, 1.0f,
        fbcv, 0, nullptr, nullptr, 0);
    tsplit2_k<<<dim3(Mm / 32, Dd / 32), tb>>>(fvh, pvhT, Mm, Dd);

    // --- q / qh (split-K=16, atomic + finalize) ---------------------------------
    split2_k<<<GRD(Bb * Dd / 4), blk>>>(x, px, Bb, Dd, Dd);
    split2_k<<<GRD(Dd * Dd / 4), blk>>>(Wq, pWq, Dd, Dd, Dd);
    zero_k<<<GRD(Bb * Dd), blk>>>(fq, Bb * Dd);
    mma_gemm<64, 128, 32, 32, 256, true><<<dim3(8, 1, 16), blk, SMEMB(64, 128)>>>(
        px, pWq, fq, Dd, 2 * Dd, 2 * Dd, Dd, 0, 0, 0, 16, 1.0f,
        nullptr, 0, nullptr, nullptr, 0);
    fin_k<<<GRD(Bb * Dd), blk>>>(fq, nullptr, pq, Bb * Dd, Dd, bq, 0, nullptr, 0);
    split2_k<<<GRD(Dd * Dd / 4), blk>>>(Wiq, pWiq, Dd, Dd, Dd);
    zero_k<<<GRD(Bb * Dd), blk>>>(fqh, Bb * Dd);
    mma_gemm<64, 128, 32, 32, 256, true><<<dim3(8, 1, 16), blk, SMEMB(64, 128)>>>(
        pq, pWiq, fqh, Dd, 2 * Dd, 2 * Dd, Dd, 0, 0, 0, 16, 1.0f,
        nullptr, 0, nullptr, nullptr, 0);
    fin_k<<<GRD(Bb * Dd), blk>>>(fqh, nullptr, pqh, Bb * Dd, Dd, biq, 0, nullptr, 1);

    // --- scores (batched per head, direct store, deterministic) -----------------
    mma_gemm<64, 128, 32, 32, 256, false><<<dim3(Mm / 128, 1, Hh), blk, SMEMB(64, 128)>>>(
        pqh, pkh, fsc, 64, 2 * Dd, 2 * Dd, Hh * Mm,
        128, 128, Mm, 1, 0.125f, nullptr, 0, nullptr, nullptr, 0);

    // --- softmax + fused [h|l] split --------------------------------------------
    softmax_split2_k<<<Bb * Hh, blk>>>(fsc, pattn);

    // --- ctx (batched per head, split-K = 32, atomic) ---------------------------
    zero_k<<<GRD(Bb * Dd), blk>>>(fctx, Bb * Dd);
    mma_gemm<64, 64, 32, 16, 256, true><<<dim3(1, 1, Hh * 32), blk, SMEMB(64, 64)>>>(
        pattn, pvhT, fctx, Mm, Hh * 2 * Mm, 2 * Mm, Dd,
        2 * Mm, (long)64 * 2 * Mm, 64, 32, 1.0f, nullptr, 0, nullptr, nullptr, 0);
    fin_k<<<GRD(Bb * Dd), blk>>>(fctx, nullptr, pctx, Bb * Dd, Dd, nullptr, 0, nullptr, 0);

    // --- ms ----------------------------------------------------------------------
    split2_k<<<GRD(Dd * Dd / 4), blk>>>(outw, poutw, Dd, Dd, Dd);
    zero_k<<<GRD(Bb * Dd), blk>>>(fms, Bb * Dd);
    mma_gemm<64, 128, 32, 32, 256, true><<<dim3(8, 1, 16), blk, SMEMB(64, 128)>>>(
        pctx, poutw, fms, Dd, 2 * Dd, 2 * Dd, Dd, 0, 0, 0, 16, 1.0f,
        nullptr, 0, nullptr, nullptr, 0);
    fin_k<<<GRD(Bb * Dd), blk>>>(fms, fms, nullptr, Bb * Dd, Dd, outb, 0, nullptr, 0);

    // --- gate path ----------------------------------------------------------------
    concat_split2_k<<<GRD(Bb * 2 * Dd), blk>>>(x, fms, pgin);
    split2_k<<<GRD(Dd * 2 * Dd / 4), blk>>>(gW1, pgW1, Dd, 2 * Dd, 2 * Dd);
    zero_k<<<GRD(Bb * Dd), blk>>>(fg1, Bb * Dd);
    mma_gemm<64, 128, 32, 32, 256, true><<<dim3(8, 1, 16), blk, SMEMB(64, 128)>>>(
        pgin, pgW1, fg1, 2 * Dd, 4 * Dd, 4 * Dd, Dd, 0, 0, 0, 16, 1.0f,
        nullptr, 0, nullptr, nullptr, 0);
    fin_k<<<GRD(Bb * Dd), blk>>>(fg1, nullptr, pg1, Bb * Dd, Dd, gb1, 1, nullptr, 0);
    split2_k<<<GRD(Dd * Dd / 4), blk>>>(gW2, pgW2, Dd, Dd, Dd);
    zero_k<<<GRD(Bb * Dd), blk>>>(fgated, Bb * Dd);
    mma_gemm<64, 128, 32, 32, 256, true><<<dim3(8, 1, 16), blk, SMEMB(64, 128)>>>(
        pg1, pgW2, fgated, Dd, 2 * Dd, 2 * Dd, Dd, 0, 0, 0, 16, 1.0f,
        nullptr, 0, nullptr, nullptr, 0);
    fin_k<<<GRD(Bb * Dd), blk>>>(fgated, fgated, nullptr, Bb * Dd, Dd, gb2, 2, fms, 0);

    // --- output path ----------------------------------------------------------------
    concat_split2_k<<<GRD(Bb * 2 * Dd), blk>>>(x, fgated, pcomb);
    split2_k<<<GRD(2 * Dd * 2 * Dd / 4), blk>>>(iW1, piW1, 2 * Dd, 2 * Dd, 2 * Dd);
    zero_k<<<GRD(Bb * 2 * Dd), blk>>>(fi1, Bb * 2 * Dd);
    mma_gemm<64, 128, 32, 32, 256, true><<<dim3(16, 1, 16), blk, SMEMB(64, 128)>>>(
        pcomb, piW1, fi1, 2 * Dd, 4 * Dd, 4 * Dd, 2 * Dd, 0, 0, 0, 16, 1.0f,
        nullptr, 0, nullptr, nullptr, 0);
    fin_k<<<GRD(Bb * 2 * Dd), blk>>>(fi1, nullptr, pi1, Bb * 2 * Dd, 2 * Dd, ib1, 1, nullptr, 0);
    split2_k<<<GRD(Dd * 2 * Dd / 4), blk>>>(iW2, piW2, Dd, 2 * Dd, 2 * Dd);
    zero_k<<<GRD(Bb * Dd), blk>>>(out, Bb * Dd);
    mma_gemm<64, 128, 32, 32, 256, true><<<dim3(8, 1, 16), blk, SMEMB(64, 128)>>>(
        pi1, piW2, out, 2 * Dd, 4 * Dd, 4 * Dd, Dd, 0, 0, 0, 16, 1.0f,
        nullptr, 0, nullptr, nullptr, 0);
    fin_k<<<GRD(Bb * Dd), blk>>>(out, out, nullptr, Bb * Dd, Dd, ib2, 0, nullptr, 0);
}

// round 13
// speedup vs baseline: 1.1936x; 1.1936x over previous
#include <cuda_runtime.h>
#include <cuda_bf16.h>
#include <math.h>
#include <stdint.h>

#define Dd 1024
#define Mm 8192
#define Hh 16
#define Bb 64

typedef __nv_bfloat16 bf16;

// ---------------- scratch (device globals) ----------------------------------
#define DA __device__ __align__(16)
DA bf16 s_WkT[Dd * 2 * Dd];
DA bf16 s_WvT[Dd * 2 * Dd];
DA bf16 s_Wik[Dd * 2 * Dd];
DA bf16 s_Wiv[Dd * 2 * Dd];
DA bf16 s_Wck[Dd * 2 * Dd];
DA bf16 s_Wcv[Dd * 2 * Dd];
DA bf16 s_keys[Mm * 2 * Dd];
DA bf16 s_vals[Mm * 2 * Dd];
DA bf16 s_kh[Mm * 2 * Dd];          // head-blocked: head h at h*128, [h(64)|l(64)]
DA bf16 s_vh2[2 * Mm * Dd];         // row-plane split: rows 0..Mm-1 = h, Mm.. = l
DA bf16 s_attn[Bb * Hh * 2 * Mm];
DA bf16 s_x[Bb * 2 * Dd];
DA bf16 s_Wq[Dd * 2 * Dd];
DA bf16 s_q[Bb * 2 * Dd];
DA bf16 s_Wiq[Dd * 2 * Dd];
DA bf16 s_qh[Bb * 2 * Dd];          // head-blocked
DA bf16 s_ctx[Bb * 2 * Dd];
DA bf16 s_outw[Dd * 2 * Dd];
DA bf16 s_gin[Bb * 4 * Dd];
DA bf16 s_gW1[Dd * 4 * Dd];
DA bf16 s_g1[Bb * 2 * Dd];
DA bf16 s_gW2[Dd * 2 * Dd];
DA bf16 s_comb[Bb * 4 * Dd];
DA bf16 s_iW1[2 * Dd * 4 * Dd];
DA bf16 s_i1[Bb * 4 * Dd];
DA bf16 s_iW2[Dd * 4 * Dd];

DA float f_part[32 * Bb * Dd];      // split-K partials (2M floats, shared)
DA float f_scores[Bb * Hh * Mm];
DA float f_ms[Bb * Dd];
DA float f_gated[Bb * Dd];
DA float f_bck[Dd];
DA float f_bcv[Dd];

// ---------------- helpers ----------------------------------------------------
__device__ __forceinline__ uint32_t sptr(const void* p)
{
    return (uint32_t)__cvta_generic_to_shared(p);
}

__device__ __forceinline__ void cpasync16(const bf16* g, uint32_t s)
{
    asm volatile("cp.async.ca.shared.global [%0], [%1], 16;" :: "r"(s), "l"(g));
}

__device__ __forceinline__ void ldm4(uint32_t s, uint32_t& r0, uint32_t& r1,
                                     uint32_t& r2, uint32_t& r3)
{
    asm volatile("ldmatrix.sync.aligned.m8n8.x4.shared.b16 {%0,%1,%2,%3}, [%4];"
                 : "=r"(r0), "=r"(r1), "=r"(r2), "=r"(r3) : "r"(s));
}

__device__ __forceinline__ void ldm4t(uint32_t s, uint32_t& r0, uint32_t& r1,
                                      uint32_t& r2, uint32_t& r3)
{
    asm volatile("ldmatrix.sync.aligned.m8n8.x4.trans.shared.b16 {%0,%1,%2,%3}, [%4];"
                 : "=r"(r0), "=r"(r1), "=r"(r2), "=r"(r3) : "r"(s));
}

__device__ __forceinline__ void mma16816(float* c, const uint32_t* a, const uint32_t* b)
{
    asm volatile(
        "mma.sync.aligned.m16n8k16.row.col.f32.bf16.bf16.f32 "
        "{%0,%1,%2,%3}, {%4,%5,%6,%7}, {%8,%9}, {%0,%1,%2,%3};"
        : "+f"(c[0]), "+f"(c[1]), "+f"(c[2]), "+f"(c[3])
        : "r"(a[0]), "r"(a[1]), "r"(a[2]), "r"(a[3]), "r"(b[0]), "r"(b[1]));
}

// write split of v.
// smode 0: col-plane [h|l]: row width 2*ldc, l at +ldc
// smode 1: head-blocked: head = cc>>6 at hd*128, l at +64; row width 2*ldc
// smode 2: row-plane: row width ldc, l plane at element offset loOff
__device__ __forceinline__ void write_split(bf16* sout, long rr, int cc, int ldc,
                                            int smode, long loOff, float v)
{
    bf16 h = __float2bfloat16(v);
    bf16 l = __float2bfloat16(v - __bfloat162float(h));
    if (smode == 2) {
        long b = rr * (long)ldc + cc;
        sout[b] = h; sout[loOff + b] = l;
    } else if (smode == 0) {
        long rb = rr * 2 * (long)ldc;
        sout[rb + cc] = h; sout[rb + ldc + cc] = l;
    } else {
        int hd = cc >> 6, j = cc & 63;
        long base = rr * 2 * (long)ldc + hd * 128 + j;
        sout[base] = h; sout[base + 64] = l;
    }
}

// ---------------- bf16-split HMMA GEMM (TN), phase-tripled ---------------------
// C = Ah*Bh + Ah*Bl + Al*Bh over base depth K1; A rows are [h|l] (lo at +K1).
// TRB=false: B rows are N x [h|l] K-major. TRB=true: B is K-major-rows [2K1 x N]
// (lo plane rows at +K1), loaded with ldmatrix.trans.
// PART: store per-split partials at C[split*sPart + ...] (no epilogue).
template <int BM, int BN, int TMW, int TNW, int NTH, bool PART, bool TRB>
__global__ void __launch_bounds__(NTH) mma_gemm(
    const bf16* __restrict__ A, const bf16* __restrict__ B, float* __restrict__ C,
    int K1, int lda, int ldb, int ldc,
    long sA, long sB, long sC, int nsplit, long sPart, float alpha,
    const float* __restrict__ bias, int act, const float* __restrict__ mul,
    bf16* __restrict__ sout, int smode, long loOff)
{
    constexpr int BK = 32, SK = 40, SKN = 72;
    constexpr int WMn = BM / TMW;
    constexpr int WNn = BN / TNW;
    static_assert(WMn * WNn * 32 == NTH, "warp layout");
    constexpr int MI = TMW / 16, NI = TNW / 8;
    static_assert((NI & 1) == 0, "NI even");
    constexpr int CA = BM * 4 / NTH;
    constexpr int CBn = TRB ? (BK * BN / 8 / NTH) : (BN * 4 / NTH);
    constexpr int BSZ = TRB ? (BK * SKN) : (BN * SK);

    extern __shared__ bf16 dsm[];
    bf16* As = dsm;                       // [3][BM*SK]
    bf16* Bs = dsm + 3 * BM * SK;         // [3][BSZ]

    const int tid = threadIdx.x;
    const int lane = tid & 31;
    const int warp = tid >> 5;
    const int wm = (warp % WMn) * TMW;
    const int wn = (warp / WMn) * TNW;

    const long z = blockIdx.z;
    const long batch = z / nsplit;
    const int split = (int)(z % nsplit);
    A += batch * sA;
    B += batch * sB;
    C += batch * sC;

    const int NTP = K1 / BK;
    const int NT = 3 * NTP;
    const int TPS = NT / nsplit;
    const int t0 = split * TPS;
    const int m0 = blockIdx.y * BM;
    const int n0 = blockIdx.x * BN;

    float acc[MI][NI][4];
#pragma unroll
    for (int i = 0; i < MI; i++)
#pragma unroll
        for (int j = 0; j < NI; j++)
#pragma unroll
            for (int q = 0; q < 4; q++) acc[i][j][q] = 0.0f;

    auto loadT = [&](int buf, int t) {
        const int p = t / NTP;
        const int ktp = t - p * NTP;
        const int Acol = ktp * BK + (p == 2 ? K1 : 0);
        bf16* Abuf = As + buf * BM * SK;
        bf16* Bbuf = Bs + buf * BSZ;
#pragma unroll
        for (int i = 0; i < CA; i++) {
            int cid = tid + i * NTH;
            int r = cid >> 2, c = (cid & 3) * 8;
            cpasync16(A + (long)(m0 + r) * lda + Acol + c, sptr(&Abuf[r * SK + c]));
        }
        if (TRB) {
            const int Brow = ktp * BK + (p == 1 ? K1 : 0);
#pragma unroll
            for (int i = 0; i < CBn; i++) {
                int cid = tid + i * NTH;
                int k = cid / (BN / 8);
                int n = (cid % (BN / 8)) * 8;
                cpasync16(B + (long)(Brow + k) * ldb + n0 + n, sptr(&Bbuf[k * SKN + n]));
            }
        } else {
            const int Bcol = ktp * BK + (p == 1 ? K1 : 0);
#pragma unroll
            for (int i = 0; i < CBn; i++) {
                int cid = tid + i * NTH;
                int r = cid >> 2, c = (cid & 3) * 8;
                cpasync16(B + (long)(n0 + r) * ldb + Bcol + c, sptr(&Bbuf[r * SK + c]));
            }
        }
        asm volatile("cp.async.commit_group;");
    };

    loadT(0, t0);
    loadT(1, t0 + 1);

    for (int i = 0; i < TPS; i++) {
        const int s = i % 3;
        if (i + 1 < TPS) asm volatile("cp.async.wait_group 1;");
        else             asm volatile("cp.async.wait_group 0;");
        __syncthreads();
        if (i + 2 < TPS) loadT((i + 2) % 3, t0 + i + 2);

        bf16* Abuf = As + s * BM * SK;
        bf16* Bbuf = Bs + s * BSZ;
#pragma unroll
        for (int ki = 0; ki < 2; ki++) {
            uint32_t a[MI][4], b[NI][2];
#pragma unroll
            for (int mi = 0; mi < MI; mi++) {
                int row = wm + mi * 16 + (lane & 15);
                int col = ki * 16 + (lane >> 4) * 8;
                ldm4(sptr(&Abuf[row * SK + col]),
                     a[mi][0], a[mi][1], a[mi][2], a[mi][3]);
            }
#pragma unroll
            for (int nj = 0; nj < NI; nj += 2) {
                uint32_t r0, r1, r2, r3;
                if (TRB) {
                    int rowk = ki * 16 + ((lane >> 4) << 3) + (lane & 7);
                    int coln = wn + nj * 8 + (((lane >> 3) & 1) << 3);
                    ldm4t(sptr(&Bbuf[rowk * SKN + coln]), r0, r1, r2, r3);
                } else {
                    int row = wn + nj * 8 + (lane & 15);
                    int col = ki * 16 + (lane >> 4) * 8;
                    ldm4(sptr(&Bbuf[row * SK + col]), r0, r1, r2, r3);
                }
                b[nj][0] = r0;     b[nj][1] = r2;
                b[nj + 1][0] = r1; b[nj + 1][1] = r3;
            }
#pragma unroll
            for (int mi = 0; mi < MI; mi++)
#pragma unroll
                for (int nj = 0; nj < NI; nj++)
                    mma16816(acc[mi][nj], a[mi], b[nj]);
        }
    }

    // ---- epilogue
#pragma unroll
    for (int mi = 0; mi < MI; mi++) {
#pragma unroll
        for (int nj = 0; nj < NI; nj++) {
            const int r = m0 + wm + mi * 16 + (lane >> 2);
            const int c = n0 + wn + nj * 8 + (lane & 3) * 2;
#pragma unroll
            for (int q = 0; q < 4; q++) {
                const int rr = r + (q >> 1) * 8;
                const int cc = c + (q & 1);
                float v = acc[mi][nj][q] * alpha;
                if (PART) {
                    C[(long)split * sPart + (long)rr * ldc + cc] = v;
                } else {
                    if (bias) v += __ldg(&bias[cc]);
                    if (act == 1) v = fmaxf(v, 0.0f);
                    else if (act == 2) v = 1.0f / (1.0f + expf(-v));
                    if (mul) v *= mul[(long)rr * ldc + cc];
                    if (C) C[(long)rr * ldc + cc] = v;
                    if (sout) write_split(sout, rr, cc, ldc, smode, loOff, v);
                }
            }
        }
    }
}

// ---------------- finalize: sum split-K partials + epilogue --------------------
__global__ void fin_sum_k(const float* __restrict__ part, float* __restrict__ fout,
                          bf16* __restrict__ sout, long n, int Kc,
                          int nsplit, long sPart,
                          const float* __restrict__ bias, int act,
                          const float* __restrict__ mul, int smode)
{
    long i = (long)blockIdx.x * 256 + threadIdx.x;
    if (i >= n) return;
    long r = i / Kc;
    int c = (int)(i % Kc);
    float v = 0.0f;
    for (int s = 0; s < nsplit; s++) v += part[s * sPart + i];
    if (bias) v += bias[c];
    if (act == 1) v = fmaxf(v, 0.0f);
    else if (act == 2) v = 1.0f / (1.0f + expf(-v));
    if (mul) v *= mul[i];
    if (fout) fout[i] = v;
    if (sout) write_split(sout, r, c, Kc, smode, 0, v);
}

// ---------------- conversion kernels -----------------------------------------
__global__ void split2_k(const float* __restrict__ in, bf16* __restrict__ out,
                         int R, int K, int ldin)
{
    long g = (long)blockIdx.x * 256 + threadIdx.x;
    if (g >= (long)R * K / 4) return;
    long i = g * 4;
    int r = (int)(i / K), k = (int)(i % K);
    float4 xv = *(const float4*)&in[(long)r * ldin + k];
    float xs[4] = {xv.x, xv.y, xv.z, xv.w};
    bf16 hs[4], ls[4];
#pragma unroll
    for (int j = 0; j < 4; j++) {
        hs[j] = __float2bfloat16(xs[j]);
        ls[j] = __float2bfloat16(xs[j] - __bfloat162float(hs[j]));
    }
    bf16* o = out + (long)r * 2 * K;
    *(uint2*)&o[k] = *(uint2*)hs;
    *(uint2*)&o[K + k] = *(uint2*)ls;
}

__global__ void tsplit2_k(const float* __restrict__ in, bf16* __restrict__ out,
                          int Kr, int Nc)
{
    __shared__ float t[32][33];
    int k0 = blockIdx.x * 32, n0 = blockIdx.y * 32;
    int tx = threadIdx.x, ty = threadIdx.y;
#pragma unroll
    for (int i = 0; i < 32; i += 8)
        t[ty + i][tx] = in[(long)(k0 + ty + i) * Nc + n0 + tx];
    __syncthreads();
#pragma unroll
    for (int i = 0; i < 32; i += 8) {
        int n = n0 + ty + i, k = k0 + tx;
        float x = t[tx][ty + i];
        bf16 h = __float2bfloat16(x);
        bf16 l = __float2bfloat16(x - __bfloat162float(h));
        bf16* o = out + (long)n * 2 * Kr + k;
        o[0] = h; o[Kr] = l;
    }
}

__global__ void concat_split2_k(const float* __restrict__ a, const float* __restrict__ b,
                                bf16* __restrict__ o)
{
    int i = blockIdx.x * 256 + threadIdx.x;
    if (i >= Bb * 2 * Dd) return;
    int r = i / (2 * Dd), c = i % (2 * Dd);
    float x = (c < Dd) ? a[r * Dd + c] : b[r * Dd + c - Dd];
    bf16 h = __float2bfloat16(x);
    bf16 l = __float2bfloat16(x - __bfloat162float(h));
    bf16* ro = o + (long)r * 4 * Dd;
    ro[c] = h; ro[2 * Dd + c] = l;
}

// ---------------- misc kernels (fp32) ----------------------------------------
__global__ void bias_combine_k(const float* __restrict__ W, const float* __restrict__ b1,
                               const float* __restrict__ b2, float* __restrict__ out)
{
    const int row = blockIdx.x * blockDim.y + threadIdx.y;
    const int lane = threadIdx.x;
    float s = 0.0f;
    for (int c = lane; c < Dd; c += 32) s += W[row * Dd + c] * b1[c];
#pragma unroll
    for (int o = 16; o; o >>= 1) s += __shfl_down_sync(0xffffffffu, s, o);
    if (lane == 0) out[row] = s + b2[row];
}

// softmax (register-cached, input untouched) + fused [h|l] col-plane split
__global__ void softmax_split2_k(const float* __restrict__ s, bf16* __restrict__ sout)
{
    const float* row = s + (size_t)blockIdx.x * Mm;
    bf16* ob = sout + (size_t)blockIdx.x * 2 * Mm;
    __shared__ float red[256];
    const int t = threadIdx.x;
    float v[Mm / 256];
    float mx = -1e30f;
#pragma unroll
    for (int j = 0; j < Mm / 256; j++) {
        v[j] = row[t + j * 256];
        mx = fmaxf(mx, v[j]);
    }
    red[t] = mx;
    __syncthreads();
    for (int o = 128; o; o >>= 1) { if (t < o) red[t] = fmaxf(red[t], red[t + o]); __syncthreads(); }
    mx = red[0];
    __syncthreads();
    float sum = 0.0f;
#pragma unroll
    for (int j = 0; j < Mm / 256; j++) { v[j] = expf(v[j] - mx); sum += v[j]; }
    red[t] = sum;
    __syncthreads();
    for (int o = 128; o; o >>= 1) { if (t < o) red[t] += red[t + o]; __syncthreads(); }
    const float inv = 1.0f / red[0];
#pragma unroll
    for (int j = 0; j < Mm / 256; j++) {
        float w = v[j] * inv;
        bf16 h = __float2bfloat16(w);
        bf16 l = __float2bfloat16(w - __bfloat162float(h));
        ob[t + j * 256] = h;
        ob[Mm + t + j * 256] = l;
    }
}

// ---------------- launch ------------------------------------------------------
#define SYM(v, g) cudaGetSymbolAddress((void**)&v, g)
#define GRD(n) dim3((unsigned)(((long)(n) + 255) / 256))
#define SMEM_TN(BM, BN) (3 * ((BM) * 40 + (BN) * 40) * (int)sizeof(bf16))
#define SMEM_TR(BM)     (3 * ((BM) * 40 + 32 * 72) * (int)sizeof(bf16))

extern "C" void kernel_launch(void* const* d_in, const int* in_sizes, int n_in,
                              void* d_out, int out_size)
{
    (void)in_sizes; (void)n_in; (void)out_size;
    const float* x    = (const float*)d_in[0];
    const float* mk   = (const float*)d_in[1];
    const float* mv   = (const float*)d_in[2];
    const float* Wq   = (const float*)d_in[3];
    const float* bq   = (const float*)d_in[4];
    const float* Wk   = (const float*)d_in[5];
    const float* bk   = (const float*)d_in[6];
    const float* Wv   = (const float*)d_in[7];
    const float* bv   = (const float*)d_in[8];
    const float* ipw  = (const float*)d_in[9];
    const float* ipb  = (const float*)d_in[10];
    const float* outw = (const float*)d_in[11];
    const float* outb = (const float*)d_in[12];
    const float* gW1  = (const float*)d_in[13];
    const float* gb1  = (const float*)d_in[14];
    const float* gW2  = (const float*)d_in[15];
    const float* gb2  = (const float*)d_in[16];
    const float* iW1  = (const float*)d_in[17];
    const float* ib1  = (const float*)d_in[18];
    const float* iW2  = (const float*)d_in[19];
    const float* ib2  = (const float*)d_in[20];
    float* out = (float*)d_out;

    const float* Wiq = ipw;
    const float* Wik = ipw + Dd * Dd;
    const float* Wiv = ipw + 2 * Dd * Dd;
    const float* biq = ipb;
    const float* bik = ipb + Dd;
    const float* biv = ipb + 2 * Dd;

    bf16 *pWkT, *pWvT, *pWik, *pWiv, *pWck, *pWcv, *pkeys, *pvals, *pkh, *pvh2, *pattn;
    bf16 *px, *pWq, *pq, *pWiq, *pqh, *pctx, *poutw, *pgin, *pgW1, *pg1, *pgW2;
    bf16 *pcomb, *piW1, *pi1, *piW2;
    float *fpart, *fsc, *fms, *fgated, *fbck, *fbcv;

    SYM(pWkT, s_WkT); SYM(pWvT, s_WvT); SYM(pWik, s_Wik); SYM(pWiv, s_Wiv);
    SYM(pWck, s_Wck); SYM(pWcv, s_Wcv); SYM(pkeys, s_keys); SYM(pvals, s_vals);
    SYM(pkh, s_kh); SYM(pvh2, s_vh2); SYM(pattn, s_attn);
    SYM(px, s_x); SYM(pWq, s_Wq); SYM(pq, s_q); SYM(pWiq, s_Wiq); SYM(pqh, s_qh);
    SYM(pctx, s_ctx); SYM(poutw, s_outw); SYM(pgin, s_gin); SYM(pgW1, s_gW1);
    SYM(pg1, s_g1); SYM(pgW2, s_gW2); SYM(pcomb, s_comb); SYM(piW1, s_iW1);
    SYM(pi1, s_i1); SYM(piW2, s_iW2);
    SYM(fpart, f_part); SYM(fsc, f_scores); SYM(fms, f_ms); SYM(fgated, f_gated);
    SYM(fbck, f_bck); SYM(fbcv, f_bcv);

    cudaFuncSetAttribute((const void*)mma_gemm<128, 128, 32, 64, 256, false, false>,
                         cudaFuncAttributeMaxDynamicSharedMemorySize, SMEM_TN(128, 128));
    cudaFuncSetAttribute((const void*)mma_gemm<64, 128, 32, 32, 256, true, false>,
                         cudaFuncAttributeMaxDynamicSharedMemorySize, SMEM_TN(64, 128));
    cudaFuncSetAttribute((const void*)mma_gemm<64, 128, 32, 32, 256, false, false>,
                         cudaFuncAttributeMaxDynamicSharedMemorySize, SMEM_TN(64, 128));
    cudaFuncSetAttribute((const void*)mma_gemm<64, 64, 32, 16, 256, true, true>,
                         cudaFuncAttributeMaxDynamicSharedMemorySize, SMEM_TR(64));

    const dim3 blk(256);
    const dim3 tb(32, 8);
    const long sPsm = (long)Bb * Dd;          // partial stride (small gemms, ctx)
    const long sPi1 = (long)Bb * 2 * Dd;      // partial stride for i1

    // --- weight combines (fused [h|l] col-plane out) -----------------------------
    tsplit2_k<<<dim3(Dd / 32, Dd / 32), tb>>>(Wk, pWkT, Dd, Dd);
    split2_k<<<GRD(Dd * Dd / 4), blk>>>(Wik, pWik, Dd, Dd, Dd);
    mma_gemm<128, 128, 32, 64, 256, false, false><<<dim3(8, 8, 1), blk, SMEM_TN(128, 128)>>>(
        pWik, pWkT, nullptr, Dd, 2 * Dd, 2 * Dd, Dd, 0, 0, 0, 1, 0, 1.0f,
        nullptr, 0, nullptr, pWck, 0, 0);
    tsplit2_k<<<dim3(Dd / 32, Dd / 32), tb>>>(Wv, pWvT, Dd, Dd);
    split2_k<<<GRD(Dd * Dd / 4), blk>>>(Wiv, pWiv, Dd, Dd, Dd);
    mma_gemm<128, 128, 32, 64, 256, false, false><<<dim3(8, 8, 1), blk, SMEM_TN(128, 128)>>>(
        pWiv, pWvT, nullptr, Dd, 2 * Dd, 2 * Dd, Dd, 0, 0, 0, 1, 0, 1.0f,
        nullptr, 0, nullptr, pWcv, 0, 0);
    bias_combine_k<<<Dd / 8, tb>>>(Wik, bk, bik, fbck);
    bias_combine_k<<<Dd / 8, tb>>>(Wiv, bv, biv, fbcv);

    // --- big GEMMs: kh (head-blocked split), vh (row-plane split, no fp32) -------
    split2_k<<<GRD((long)Mm * Dd / 4), blk>>>(mk, pkeys, Mm, Dd, Dd);
    split2_k<<<GRD((long)Mm * Dd / 4), blk>>>(mv, pvals, Mm, Dd, Dd);
    mma_gemm<128, 128, 32, 64, 256, false, false><<<dim3(8, 64, 1), blk, SMEM_TN(128, 128)>>>(
        pkeys, pWck, nullptr, Dd, 2 * Dd, 2 * Dd, Dd, 0, 0, 0, 1, 0, 1.0f,
        fbck, 0, nullptr, pkh, 1, 0);
    mma_gemm<128, 128, 32, 64, 256, false, false><<<dim3(8, 64, 1), blk, SMEM_TN(128, 128)>>>(
        pvals, pWcv, nullptr, Dd, 2 * Dd, 2 * Dd, Dd, 0, 0, 0, 1, 0, 1.0f,
        fbcv, 0, nullptr, pvh2, 2, (long)Mm * Dd);

    // --- q / qh (split-K=16, partials + fin_sum) ----------------------------------
    split2_k<<<GRD(Bb * Dd / 4), blk>>>(x, px, Bb, Dd, Dd);
    split2_k<<<GRD(Dd * Dd / 4), blk>>>(Wq, pWq, Dd, Dd, Dd);
    mma_gemm<64, 128, 32, 32, 256, true, false><<<dim3(8, 1, 16), blk, SMEM_TN(64, 128)>>>(
        px, pWq, fpart, Dd, 2 * Dd, 2 * Dd, Dd, 0, 0, 0, 16, sPsm, 1.0f,
        nullptr, 0, nullptr, nullptr, 0, 0);
    fin_sum_k<<<GRD(Bb * Dd), blk>>>(fpart, nullptr, pq, Bb * Dd, Dd, 16, sPsm,
                                     bq, 0, nullptr, 0);
    split2_k<<<GRD(Dd * Dd / 4), blk>>>(Wiq, pWiq, Dd, Dd, Dd);
    mma_gemm<64, 128, 32, 32, 256, true, false><<<dim3(8, 1, 16), blk, SMEM_TN(64, 128)>>>(
        pq, pWiq, fpart, Dd, 2 * Dd, 2 * Dd, Dd, 0, 0, 0, 16, sPsm, 1.0f,
        nullptr, 0, nullptr, nullptr, 0, 0);
    fin_sum_k<<<GRD(Bb * Dd), blk>>>(fpart, nullptr, pqh, Bb * Dd, Dd, 16, sPsm,
                                     biq, 0, nullptr, 1);

    // --- scores (batched per head, direct store) -----------------------------------
    mma_gemm<64, 128, 32, 32, 256, false, false><<<dim3(Mm / 128, 1, Hh), blk, SMEM_TN(64, 128)>>>(
        pqh, pkh, fsc, 64, 2 * Dd, 2 * Dd, Hh * Mm,
        128, 128, Mm, 1, 0, 0.125f, nullptr, 0, nullptr, nullptr, 0, 0);

    // --- softmax + fused split -------------------------------------------------------
    softmax_split2_k<<<Bb * Hh, blk>>>(fsc, pattn);

    // --- ctx (per head, NN-B via ldmatrix.trans, split-K=32 partials) ---------------
    mma_gemm<64, 64, 32, 16, 256, true, true><<<dim3(1, 1, Hh * 32), blk, SMEM_TR(64)>>>(
        pattn, pvh2, fpart, Mm, Hh * 2 * Mm, Dd, Dd,
        2 * Mm, 64, 64, 32, sPsm, 1.0f, nullptr, 0, nullptr, nullptr, 0, 0);
    fin_sum_k<<<GRD(Bb * Dd), blk>>>(fpart, nullptr, pctx, Bb * Dd, Dd, 32, sPsm,
                                     nullptr, 0, nullptr, 0);

    // --- ms ----------------------------------------------------------------------------
    split2_k<<<GRD(Dd * Dd / 4), blk>>>(outw, poutw, Dd, Dd, Dd);
    mma_gemm<64, 128, 32, 32, 256, true, false><<<dim3(8, 1, 16), blk, SMEM_TN(64, 128)>>>(
        pctx, poutw, fpart, Dd, 2 * Dd, 2 * Dd, Dd, 0, 0, 0, 16, sPsm, 1.0f,
        nullptr, 0, nullptr, nullptr, 0, 0);
    fin_sum_k<<<GRD(Bb * Dd), blk>>>(fpart, fms, nullptr, Bb * Dd, Dd, 16, sPsm,
                                     outb, 0, nullptr, 0);

    // --- gate path -----------------------------------------------------------------------
    concat_split2_k<<<GRD(Bb * 2 * Dd), blk>>>(x, fms, pgin);
    split2_k<<<GRD(Dd * 2 * Dd / 4), blk>>>(gW1, pgW1, Dd, 2 * Dd, 2 * Dd);
    mma_gemm<64, 128, 32, 32, 256, true, false><<<dim3(8, 1, 16), blk, SMEM_TN(64, 128)>>>(
        pgin, pgW1, fpart, 2 * Dd, 4 * Dd, 4 * Dd, Dd, 0, 0, 0, 16, sPsm, 1.0f,
        nullptr, 0, nullptr, nullptr, 0, 0);
    fin_sum_k<<<GRD(Bb * Dd), blk>>>(fpart, nullptr, pg1, Bb * Dd, Dd, 16, sPsm,
                                     gb1, 1, nullptr, 0);
    split2_k<<<GRD(Dd * Dd / 4), blk>>>(gW2, pgW2, Dd, Dd, Dd);
    mma_gemm<64, 128, 32, 32, 256, true, false><<<dim3(8, 1, 16), blk, SMEM_TN(64, 128)>>>(
        pg1, pgW2, fpart, Dd, 2 * Dd, 2 * Dd, Dd, 0, 0, 0, 16, sPsm, 1.0f,
        nullptr, 0, nullptr, nullptr, 0, 0);
    fin_sum_k<<<GRD(Bb * Dd), blk>>>(fpart, fgated, nullptr, Bb * Dd, Dd, 16, sPsm,
                                     gb2, 2, fms, 0);

    // --- output path ----------------------------------------------------------------------
    concat_split2_k<<<GRD(Bb * 2 * Dd), blk>>>(x, fgated, pcomb);
    split2_k<<<GRD(2 * Dd * 2 * Dd / 4), blk>>>(iW1, piW1, 2 * Dd, 2 * Dd, 2 * Dd);
    mma_gemm<64, 128, 32, 32, 256, true, false><<<dim3(16, 1, 16), blk, SMEM_TN(64, 128)>>>(
        pcomb, piW1, fpart, 2 * Dd, 4 * Dd, 4 * Dd, 2 * Dd, 0, 0, 0, 16, sPi1, 1.0f,
        nullptr, 0, nullptr, nullptr, 0, 0);
    fin_sum_k<<<GRD(Bb * 2 * Dd), blk>>>(fpart, nullptr, pi1, Bb * 2 * Dd, 2 * Dd, 16, sPi1,
                                         ib1, 1, nullptr, 0);
    split2_k<<<GRD(Dd * 2 * Dd / 4), blk>>>(iW2, piW2, Dd, 2 * Dd, 2 * Dd);
    mma_gemm<64, 128, 32, 32, 256, true, false><<<dim3(8, 1, 16), blk, SMEM_TN(64, 128)>>>(
        pi1, piW2, fpart, 2 * Dd, 4 * Dd, 4 * Dd, Dd, 0, 0, 0, 16, sPsm, 1.0f,
        nullptr, 0, nullptr, nullptr, 0, 0);
    fin_sum_k<<<GRD(Bb * Dd), blk>>>(fpart, out, nullptr, Bb * Dd, Dd, 16, sPsm,
                                     ib2, 0, nullptr, 0);
}

// round 14
// speedup vs baseline: 1.5031x; 1.2593x over previous
#include <cuda_runtime.h>
#include <cuda_bf16.h>
#include <math.h>
#include <stdint.h>

#define Dd 1024
#define Mm 8192
#define Hh 16
#define Bb 64

typedef __nv_bfloat16 bf16;

// ---------------- scratch (device globals) ----------------------------------
#define DA __device__ __align__(16)
DA bf16 s_WkT[Dd * 2 * Dd];
DA bf16 s_WvT[Dd * 2 * Dd];
DA bf16 s_Wik[Dd * 2 * Dd];
DA bf16 s_Wiv[Dd * 2 * Dd];
DA bf16 s_Wck[Dd * 2 * Dd];
DA bf16 s_Wcv[Dd * 2 * Dd];
DA bf16 s_keys[Mm * 2 * Dd];
DA bf16 s_vals[Mm * 2 * Dd];
DA bf16 s_kh[Mm * 2 * Dd];          // head-blocked: head h at h*128, [h(64)|l(64)]
DA bf16 s_vh2[2 * Mm * Dd];         // row-plane split: rows 0..Mm-1 = h, Mm.. = l
DA bf16 s_attn[Bb * Hh * 2 * Mm];
DA bf16 s_x[Bb * 2 * Dd];
DA bf16 s_Wq[Dd * 2 * Dd];
DA bf16 s_q[Bb * 2 * Dd];
DA bf16 s_Wiq[Dd * 2 * Dd];
DA bf16 s_qh[Bb * 2 * Dd];          // head-blocked
DA bf16 s_ctx[Bb * 2 * Dd];
DA bf16 s_outw[Dd * 2 * Dd];
DA bf16 s_gin[Bb * 4 * Dd];
DA bf16 s_gW1[Dd * 4 * Dd];
DA bf16 s_g1[Bb * 2 * Dd];
DA bf16 s_gW2[Dd * 2 * Dd];
DA bf16 s_comb[Bb * 4 * Dd];
DA bf16 s_iW1[2 * Dd * 4 * Dd];
DA bf16 s_i1[Bb * 4 * Dd];
DA bf16 s_iW2[Dd * 4 * Dd];

DA float f_part[32 * Bb * Dd];      // split-K partials (2M floats, shared)
DA float f_scores[Bb * Hh * Mm];
DA float f_ms[Bb * Dd];
DA float f_gated[Bb * Dd];
DA float f_bcv[Dd];

// ---------------- helpers ----------------------------------------------------
__device__ __forceinline__ uint32_t sptr(const void* p)
{
    return (uint32_t)__cvta_generic_to_shared(p);
}

__device__ __forceinline__ void cpasync16(const bf16* g, uint32_t s)
{
    asm volatile("cp.async.ca.shared.global [%0], [%1], 16;" :: "r"(s), "l"(g));
}

__device__ __forceinline__ void ldm4(uint32_t s, uint32_t& r0, uint32_t& r1,
                                     uint32_t& r2, uint32_t& r3)
{
    asm volatile("ldmatrix.sync.aligned.m8n8.x4.shared.b16 {%0,%1,%2,%3}, [%4];"
                 : "=r"(r0), "=r"(r1), "=r"(r2), "=r"(r3) : "r"(s));
}

__device__ __forceinline__ void ldm4t(uint32_t s, uint32_t& r0, uint32_t& r1,
                                      uint32_t& r2, uint32_t& r3)
{
    asm volatile("ldmatrix.sync.aligned.m8n8.x4.trans.shared.b16 {%0,%1,%2,%3}, [%4];"
                 : "=r"(r0), "=r"(r1), "=r"(r2), "=r"(r3) : "r"(s));
}

__device__ __forceinline__ void mma16816(float* c, const uint32_t* a, const uint32_t* b)
{
    asm volatile(
        "mma.sync.aligned.m16n8k16.row.col.f32.bf16.bf16.f32 "
        "{%0,%1,%2,%3}, {%4,%5,%6,%7}, {%8,%9}, {%0,%1,%2,%3};"
        : "+f"(c[0]), "+f"(c[1]), "+f"(c[2]), "+f"(c[3])
        : "r"(a[0]), "r"(a[1]), "r"(a[2]), "r"(a[3]), "r"(b[0]), "r"(b[1]));
}

// write split of v.
// smode 0: col-plane [h|l]: row width 2*ldc, l at +ldc
// smode 1: head-blocked: head = cc>>6 at hd*128, l at +64; row width 2*ldc
// smode 2: row-plane: row width ldc, l plane at element offset loOff
__device__ __forceinline__ void write_split(bf16* sout, long rr, int cc, int ldc,
                                            int smode, long loOff, float v)
{
    bf16 h = __float2bfloat16(v);
    bf16 l = __float2bfloat16(v - __bfloat162float(h));
    if (smode == 2) {
        long b = rr * (long)ldc + cc;
        sout[b] = h; sout[loOff + b] = l;
    } else if (smode == 0) {
        long rb = rr * 2 * (long)ldc;
        sout[rb + cc] = h; sout[rb + ldc + cc] = l;
    } else {
        int hd = cc >> 6, j = cc & 63;
        long base = rr * 2 * (long)ldc + hd * 128 + j;
        sout[base] = h; sout[base + 64] = l;
    }
}

// ---------------- bf16-split HMMA GEMM (TN), phase-tripled ---------------------
template <int BM, int BN, int TMW, int TNW, int NTH, bool PART, bool TRB>
__global__ void __launch_bounds__(NTH) mma_gemm(
    const bf16* __restrict__ A, const bf16* __restrict__ B, float* __restrict__ C,
    int K1, int lda, int ldb, int ldc,
    long sA, long sB, long sC, int nsplit, long sPart, float alpha,
    const float* __restrict__ bias, int act, const float* __restrict__ mul,
    bf16* __restrict__ sout, int smode, long loOff)
{
    constexpr int BK = 32, SK = 40, SKN = 72;
    constexpr int WMn = BM / TMW;
    constexpr int WNn = BN / TNW;
    static_assert(WMn * WNn * 32 == NTH, "warp layout");
    constexpr int MI = TMW / 16, NI = TNW / 8;
    static_assert((NI & 1) == 0, "NI even");
    constexpr int CA = BM * 4 / NTH;
    constexpr int CBn = TRB ? (BK * BN / 8 / NTH) : (BN * 4 / NTH);
    constexpr int BSZ = TRB ? (BK * SKN) : (BN * SK);

    extern __shared__ bf16 dsm[];
    bf16* As = dsm;                       // [3][BM*SK]
    bf16* Bs = dsm + 3 * BM * SK;         // [3][BSZ]

    const int tid = threadIdx.x;
    const int lane = tid & 31;
    const int warp = tid >> 5;
    const int wm = (warp % WMn) * TMW;
    const int wn = (warp / WMn) * TNW;

    const long z = blockIdx.z;
    const long batch = z / nsplit;
    const int split = (int)(z % nsplit);
    A += batch * sA;
    B += batch * sB;
    C += batch * sC;

    const int NTP = K1 / BK;
    const int NT = 3 * NTP;
    const int TPS = NT / nsplit;
    const int t0 = split * TPS;
    const int m0 = blockIdx.y * BM;
    const int n0 = blockIdx.x * BN;

    float acc[MI][NI][4];
#pragma unroll
    for (int i = 0; i < MI; i++)
#pragma unroll
        for (int j = 0; j < NI; j++)
#pragma unroll
            for (int q = 0; q < 4; q++) acc[i][j][q] = 0.0f;

    auto loadT = [&](int buf, int t) {
        const int p = t / NTP;
        const int ktp = t - p * NTP;
        const int Acol = ktp * BK + (p == 2 ? K1 : 0);
        bf16* Abuf = As + buf * BM * SK;
        bf16* Bbuf = Bs + buf * BSZ;
#pragma unroll
        for (int i = 0; i < CA; i++) {
            int cid = tid + i * NTH;
            int r = cid >> 2, c = (cid & 3) * 8;
            cpasync16(A + (long)(m0 + r) * lda + Acol + c, sptr(&Abuf[r * SK + c]));
        }
        if (TRB) {
            const int Brow = ktp * BK + (p == 1 ? K1 : 0);
#pragma unroll
            for (int i = 0; i < CBn; i++) {
                int cid = tid + i * NTH;
                int k = cid / (BN / 8);
                int n = (cid % (BN / 8)) * 8;
                cpasync16(B + (long)(Brow + k) * ldb + n0 + n, sptr(&Bbuf[k * SKN + n]));
            }
        } else {
            const int Bcol = ktp * BK + (p == 1 ? K1 : 0);
#pragma unroll
            for (int i = 0; i < CBn; i++) {
                int cid = tid + i * NTH;
                int r = cid >> 2, c = (cid & 3) * 8;
                cpasync16(B + (long)(n0 + r) * ldb + Bcol + c, sptr(&Bbuf[r * SK + c]));
            }
        }
        asm volatile("cp.async.commit_group;");
    };

    loadT(0, t0);
    loadT(1, t0 + 1);

    for (int i = 0; i < TPS; i++) {
        const int s = i % 3;
        if (i + 1 < TPS) asm volatile("cp.async.wait_group 1;");
        else             asm volatile("cp.async.wait_group 0;");
        __syncthreads();
        if (i + 2 < TPS) loadT((i + 2) % 3, t0 + i + 2);

        bf16* Abuf = As + s * BM * SK;
        bf16* Bbuf = Bs + s * BSZ;
#pragma unroll
        for (int ki = 0; ki < 2; ki++) {
            uint32_t a[MI][4], b[NI][2];
#pragma unroll
            for (int mi = 0; mi < MI; mi++) {
                int row = wm + mi * 16 + (lane & 15);
                int col = ki * 16 + (lane >> 4) * 8;
                ldm4(sptr(&Abuf[row * SK + col]),
                     a[mi][0], a[mi][1], a[mi][2], a[mi][3]);
            }
#pragma unroll
            for (int nj = 0; nj < NI; nj += 2) {
                uint32_t r0, r1, r2, r3;
                if (TRB) {
                    int rowk = ki * 16 + ((lane >> 4) << 3) + (lane & 7);
                    int coln = wn + nj * 8 + (((lane >> 3) & 1) << 3);
                    ldm4t(sptr(&Bbuf[rowk * SKN + coln]), r0, r1, r2, r3);
                } else {
                    int row = wn + nj * 8 + (lane & 15);
                    int col = ki * 16 + (lane >> 4) * 8;
                    ldm4(sptr(&Bbuf[row * SK + col]), r0, r1, r2, r3);
                }
                b[nj][0] = r0;     b[nj][1] = r2;
                b[nj + 1][0] = r1; b[nj + 1][1] = r3;
            }
#pragma unroll
            for (int mi = 0; mi < MI; mi++)
#pragma unroll
                for (int nj = 0; nj < NI; nj++)
                    mma16816(acc[mi][nj], a[mi], b[nj]);
        }
    }

    // ---- epilogue
#pragma unroll
    for (int mi = 0; mi < MI; mi++) {
#pragma unroll
        for (int nj = 0; nj < NI; nj++) {
            const int r = m0 + wm + mi * 16 + (lane >> 2);
            const int c = n0 + wn + nj * 8 + (lane & 3) * 2;
#pragma unroll
            for (int q = 0; q < 4; q++) {
                const int rr = r + (q >> 1) * 8;
                const int cc = c + (q & 1);
                float v = acc[mi][nj][q] * alpha;
                if (PART) {
                    C[(long)split * sPart + (long)rr * ldc + cc] = v;
                } else {
                    if (bias) v += __ldg(&bias[cc]);
                    if (act == 1) v = fmaxf(v, 0.0f);
                    else if (act == 2) v = 1.0f / (1.0f + expf(-v));
                    if (mul) v *= mul[(long)rr * ldc + cc];
                    if (C) C[(long)rr * ldc + cc] = v;
                    if (sout) write_split(sout, rr, cc, ldc, smode, loOff, v);
                }
            }
        }
    }
}

// ---------------- finalize: sum split-K partials + epilogue --------------------
__global__ void fin_sum_k(const float* __restrict__ part, float* __restrict__ fout,
                          bf16* __restrict__ sout, long n, int Kc,
                          int nsplit, long sPart,
                          const float* __restrict__ bias, int act,
                          const float* __restrict__ mul, int smode)
{
    long i = (long)blockIdx.x * 256 + threadIdx.x;
    if (i >= n) return;
    long r = i / Kc;
    int c = (int)(i % Kc);
    float v = 0.0f;
    for (int s = 0; s < nsplit; s++) v += part[s * sPart + i];
    if (bias) v += bias[c];
    if (act == 1) v = fmaxf(v, 0.0f);
    else if (act == 2) v = 1.0f / (1.0f + expf(-v));
    if (mul) v *= mul[i];
    if (fout) fout[i] = v;
    if (sout) write_split(sout, r, c, Kc, smode, 0, v);
}

// ---------------- conversion kernels -----------------------------------------
__global__ void split2_k(const float* __restrict__ in, bf16* __restrict__ out,
                         int R, int K, int ldin)
{
    long g = (long)blockIdx.x * 256 + threadIdx.x;
    if (g >= (long)R * K / 4) return;
    long i = g * 4;
    int r = (int)(i / K), k = (int)(i % K);
    float4 xv = *(const float4*)&in[(long)r * ldin + k];
    float xs[4] = {xv.x, xv.y, xv.z, xv.w};
    bf16 hs[4], ls[4];
#pragma unroll
    for (int j = 0; j < 4; j++) {
        hs[j] = __float2bfloat16(xs[j]);
        ls[j] = __float2bfloat16(xs[j] - __bfloat162float(hs[j]));
    }
    bf16* o = out + (long)r * 2 * K;
    *(uint2*)&o[k] = *(uint2*)hs;
    *(uint2*)&o[K + k] = *(uint2*)ls;
}

__global__ void tsplit2_k(const float* __restrict__ in, bf16* __restrict__ out,
                          int Kr, int Nc)
{
    __shared__ float t[32][33];
    int k0 = blockIdx.x * 32, n0 = blockIdx.y * 32;
    int tx = threadIdx.x, ty = threadIdx.y;
#pragma unroll
    for (int i = 0; i < 32; i += 8)
        t[ty + i][tx] = in[(long)(k0 + ty + i) * Nc + n0 + tx];
    __syncthreads();
#pragma unroll
    for (int i = 0; i < 32; i += 8) {
        int n = n0 + ty + i, k = k0 + tx;
        float x = t[tx][ty + i];
        bf16 h = __float2bfloat16(x);
        bf16 l = __float2bfloat16(x - __bfloat162float(h));
        bf16* o = out + (long)n * 2 * Kr + k;
        o[0] = h; o[Kr] = l;
    }
}

__global__ void concat_split2_k(const float* __restrict__ a, const float* __restrict__ b,
                                bf16* __restrict__ o)
{
    int i = blockIdx.x * 256 + threadIdx.x;
    if (i >= Bb * 2 * Dd) return;
    int r = i / (2 * Dd), c = i % (2 * Dd);
    float x = (c < Dd) ? a[r * Dd + c] : b[r * Dd + c - Dd];
    bf16 h = __float2bfloat16(x);
    bf16 l = __float2bfloat16(x - __bfloat162float(h));
    bf16* ro = o + (long)r * 4 * Dd;
    ro[c] = h; ro[2 * Dd + c] = l;
}

// ---------------- misc kernels (fp32) ----------------------------------------
__global__ void bias_combine_k(const float* __restrict__ W, const float* __restrict__ b1,
                               const float* __restrict__ b2, float* __restrict__ out)
{
    const int row = blockIdx.x * blockDim.y + threadIdx.y;
    const int lane = threadIdx.x;
    float s = 0.0f;
    for (int c = lane; c < Dd; c += 32) s += W[row * Dd + c] * b1[c];
#pragma unroll
    for (int o = 16; o; o >>= 1) s += __shfl_down_sync(0xffffffffu, s, o);
    if (lane == 0) out[row] = s + b2[row];
}

// softmax (register-cached, input untouched) + fused [h|l] col-plane split
__global__ void softmax_split2_k(const float* __restrict__ s, bf16* __restrict__ sout)
{
    const float* row = s + (size_t)blockIdx.x * Mm;
    bf16* ob = sout + (size_t)blockIdx.x * 2 * Mm;
    __shared__ float red[256];
    const int t = threadIdx.x;
    float v[Mm / 256];
    float mx = -1e30f;
#pragma unroll
    for (int j = 0; j < Mm / 256; j++) {
        v[j] = row[t + j * 256];
        mx = fmaxf(mx, v[j]);
    }
    red[t] = mx;
    __syncthreads();
    for (int o = 128; o; o >>= 1) { if (t < o) red[t] = fmaxf(red[t], red[t + o]); __syncthreads(); }
    mx = red[0];
    __syncthreads();
    float sum = 0.0f;
#pragma unroll
    for (int j = 0; j < Mm / 256; j++) { v[j] = expf(v[j] - mx); sum += v[j]; }
    red[t] = sum;
    __syncthreads();
    for (int o = 128; o; o >>= 1) { if (t < o) red[t] += red[t + o]; __syncthreads(); }
    const float inv = 1.0f / red[0];
#pragma unroll
    for (int j = 0; j < Mm / 256; j++) {
        float w = v[j] * inv;
        bf16 h = __float2bfloat16(w);
        bf16 l = __float2bfloat16(w - __bfloat162float(h));
        ob[t + j * 256] = h;
        ob[Mm + t + j * 256] = l;
    }
}

// ---------------- launch ------------------------------------------------------
#define SYM(v, g) cudaGetSymbolAddress((void**)&v, g)
#define GRD(n) dim3((unsigned)(((long)(n) + 255) / 256))
#define SMEM_TN(BM, BN) (3 * ((BM) * 40 + (BN) * 40) * (int)sizeof(bf16))
#define SMEM_TR(BM)     (3 * ((BM) * 40 + 32 * 72) * (int)sizeof(bf16))

extern "C" void kernel_launch(void* const* d_in, const int* in_sizes, int n_in,
                              void* d_out, int out_size)
{
    (void)in_sizes; (void)n_in; (void)out_size;
    const float* x    = (const float*)d_in[0];
    const float* mk   = (const float*)d_in[1];
    const float* mv   = (const float*)d_in[2];
    const float* Wq   = (const float*)d_in[3];
    const float* bq   = (const float*)d_in[4];
    const float* Wk   = (const float*)d_in[5];
    const float* bk   = (const float*)d_in[6];
    const float* Wv   = (const float*)d_in[7];
    const float* bv   = (const float*)d_in[8];
    const float* ipw  = (const float*)d_in[9];
    const float* ipb  = (const float*)d_in[10];
    const float* outw = (const float*)d_in[11];
    const float* outb = (const float*)d_in[12];
    const float* gW1  = (const float*)d_in[13];
    const float* gb1  = (const float*)d_in[14];
    const float* gW2  = (const float*)d_in[15];
    const float* gb2  = (const float*)d_in[16];
    const float* iW1  = (const float*)d_in[17];
    const float* ib1  = (const float*)d_in[18];
    const float* iW2  = (const float*)d_in[19];
    const float* ib2  = (const float*)d_in[20];
    float* out = (float*)d_out;

    const float* Wiq = ipw;
    const float* Wik = ipw + Dd * Dd;
    const float* Wiv = ipw + 2 * Dd * Dd;
    const float* biq = ipb;
    const float* biv = ipb + 2 * Dd;

    bf16 *pWkT, *pWvT, *pWik, *pWiv, *pWck, *pWcv, *pkeys, *pvals, *pkh, *pvh2, *pattn;
    bf16 *px, *pWq, *pq, *pWiq, *pqh, *pctx, *poutw, *pgin, *pgW1, *pg1, *pgW2;
    bf16 *pcomb, *piW1, *pi1, *piW2;
    float *fpart, *fsc, *fms, *fgated, *fbcv;

    SYM(pWkT, s_WkT); SYM(pWvT, s_WvT); SYM(pWik, s_Wik); SYM(pWiv, s_Wiv);
    SYM(pWck, s_Wck); SYM(pWcv, s_Wcv); SYM(pkeys, s_keys); SYM(pvals, s_vals);
    SYM(pkh, s_kh); SYM(pvh2, s_vh2); SYM(pattn, s_attn);
    SYM(px, s_x); SYM(pWq, s_Wq); SYM(pq, s_q); SYM(pWiq, s_Wiq); SYM(pqh, s_qh);
    SYM(pctx, s_ctx); SYM(poutw, s_outw); SYM(pgin, s_gin); SYM(pgW1, s_gW1);
    SYM(pg1, s_g1); SYM(pgW2, s_gW2); SYM(pcomb, s_comb); SYM(piW1, s_iW1);
    SYM(pi1, s_i1); SYM(piW2, s_iW2);
    SYM(fpart, f_part); SYM(fsc, f_scores); SYM(fms, f_ms); SYM(fgated, f_gated);
    SYM(fbcv, f_bcv);

    cudaFuncSetAttribute((const void*)mma_gemm<128, 128, 32, 64, 256, false, false>,
                         cudaFuncAttributeMaxDynamicSharedMemorySize, SMEM_TN(128, 128));
    cudaFuncSetAttribute((const void*)mma_gemm<64, 128, 32, 32, 256, true, false>,
                         cudaFuncAttributeMaxDynamicSharedMemorySize, SMEM_TN(64, 128));
    cudaFuncSetAttribute((const void*)mma_gemm<64, 128, 32, 32, 256, false, false>,
                         cudaFuncAttributeMaxDynamicSharedMemorySize, SMEM_TN(64, 128));
    cudaFuncSetAttribute((const void*)mma_gemm<64, 64, 32, 16, 256, true, true>,
                         cudaFuncAttributeMaxDynamicSharedMemorySize, SMEM_TR(64));

    // --- one-time stream/event resources (no device memory involved) ----------
    static cudaStream_t s1 = nullptr, s2 = nullptr;
    static cudaEvent_t eFork = nullptr, eK = nullptr, eV = nullptr;
    if (!s1) {
        cudaStreamCreateWithFlags(&s1, cudaStreamNonBlocking);
        cudaStreamCreateWithFlags(&s2, cudaStreamNonBlocking);
        cudaEventCreateWithFlags(&eFork, cudaEventDisableTiming);
        cudaEventCreateWithFlags(&eK, cudaEventDisableTiming);
        cudaEventCreateWithFlags(&eV, cudaEventDisableTiming);
    }

    const dim3 blk(256);
    const dim3 tb(32, 8);
    const long sPsm = (long)Bb * Dd;
    const long sPi1 = (long)Bb * 2 * Dd;

    // ---- fork -------------------------------------------------------------------
    cudaEventRecord(eFork, 0);
    cudaStreamWaitEvent(s1, eFork, 0);
    cudaStreamWaitEvent(s2, eFork, 0);

    // ---- s1: K chain (no bias needed: softmax is shift-invariant per row) -------
    tsplit2_k<<<dim3(Dd / 32, Dd / 32), tb, 0, s1>>>(Wk, pWkT, Dd, Dd);
    split2_k<<<GRD(Dd * Dd / 4), blk, 0, s1>>>(Wik, pWik, Dd, Dd, Dd);
    split2_k<<<GRD((long)Mm * Dd / 4), blk, 0, s1>>>(mk, pkeys, Mm, Dd, Dd);
    mma_gemm<128, 128, 32, 64, 256, false, false><<<dim3(8, 8, 1), blk, SMEM_TN(128, 128), s1>>>(
        pWik, pWkT, nullptr, Dd, 2 * Dd, 2 * Dd, Dd, 0, 0, 0, 1, 0, 1.0f,
        nullptr, 0, nullptr, pWck, 0, 0);
    mma_gemm<128, 128, 32, 64, 256, false, false><<<dim3(8, 64, 1), blk, SMEM_TN(128, 128), s1>>>(
        pkeys, pWck, nullptr, Dd, 2 * Dd, 2 * Dd, Dd, 0, 0, 0, 1, 0, 1.0f,
        nullptr, 0, nullptr, pkh, 1, 0);
    cudaEventRecord(eK, s1);

    // ---- s2: V chain (bcv deferred to ctx finalize since sum(attn)=1) ------------
    tsplit2_k<<<dim3(Dd / 32, Dd / 32), tb, 0, s2>>>(Wv, pWvT, Dd, Dd);
    split2_k<<<GRD(Dd * Dd / 4), blk, 0, s2>>>(Wiv, pWiv, Dd, Dd, Dd);
    split2_k<<<GRD((long)Mm * Dd / 4), blk, 0, s2>>>(mv, pvals, Mm, Dd, Dd);
    mma_gemm<128, 128, 32, 64, 256, false, false><<<dim3(8, 8, 1), blk, SMEM_TN(128, 128), s2>>>(
        pWiv, pWvT, nullptr, Dd, 2 * Dd, 2 * Dd, Dd, 0, 0, 0, 1, 0, 1.0f,
        nullptr, 0, nullptr, pWcv, 0, 0);
    mma_gemm<128, 128, 32, 64, 256, false, false><<<dim3(8, 64, 1), blk, SMEM_TN(128, 128), s2>>>(
        pvals, pWcv, nullptr, Dd, 2 * Dd, 2 * Dd, Dd, 0, 0, 0, 1, 0, 1.0f,
        nullptr, 0, nullptr, pvh2, 2, (long)Mm * Dd);
    cudaEventRecord(eV, s2);

    // ---- origin: bias prep, weight splits, q/qh chain -----------------------------
    bias_combine_k<<<Dd / 8, tb>>>(Wiv, bv, biv, fbcv);
    split2_k<<<GRD(Bb * Dd / 4), blk>>>(x, px, Bb, Dd, Dd);
    split2_k<<<GRD(Dd * Dd / 4), blk>>>(Wq, pWq, Dd, Dd, Dd);
    split2_k<<<GRD(Dd * Dd / 4), blk>>>(Wiq, pWiq, Dd, Dd, Dd);
    split2_k<<<GRD(Dd * Dd / 4), blk>>>(outw, poutw, Dd, Dd, Dd);
    split2_k<<<GRD(Dd * 2 * Dd / 4), blk>>>(gW1, pgW1, Dd, 2 * Dd, 2 * Dd);
    split2_k<<<GRD(Dd * Dd / 4), blk>>>(gW2, pgW2, Dd, Dd, Dd);
    split2_k<<<GRD(2 * Dd * 2 * Dd / 4), blk>>>(iW1, piW1, 2 * Dd, 2 * Dd, 2 * Dd);
    split2_k<<<GRD(Dd * 2 * Dd / 4), blk>>>(iW2, piW2, Dd, 2 * Dd, 2 * Dd);

    mma_gemm<64, 128, 32, 32, 256, true, false><<<dim3(8, 1, 16), blk, SMEM_TN(64, 128)>>>(
        px, pWq, fpart, Dd, 2 * Dd, 2 * Dd, Dd, 0, 0, 0, 16, sPsm, 1.0f,
        nullptr, 0, nullptr, nullptr, 0, 0);
    fin_sum_k<<<GRD(Bb * Dd), blk>>>(fpart, nullptr, pq, Bb * Dd, Dd, 16, sPsm,
                                     bq, 0, nullptr, 0);
    mma_gemm<64, 128, 32, 32, 256, true, false><<<dim3(8, 1, 16), blk, SMEM_TN(64, 128)>>>(
        pq, pWiq, fpart, Dd, 2 * Dd, 2 * Dd, Dd, 0, 0, 0, 16, sPsm, 1.0f,
        nullptr, 0, nullptr, nullptr, 0, 0);
    fin_sum_k<<<GRD(Bb * Dd), blk>>>(fpart, nullptr, pqh, Bb * Dd, Dd, 16, sPsm,
                                     biq, 0, nullptr, 1);

    // ---- join K: scores + softmax --------------------------------------------------
    cudaStreamWaitEvent(0, eK, 0);
    mma_gemm<64, 128, 32, 32, 256, false, false><<<dim3(Mm / 128, 1, Hh), blk, SMEM_TN(64, 128)>>>(
        pqh, pkh, fsc, 64, 2 * Dd, 2 * Dd, Hh * Mm,
        128, 128, Mm, 1, 0, 0.125f, nullptr, 0, nullptr, nullptr, 0, 0);
    softmax_split2_k<<<Bb * Hh, blk>>>(fsc, pattn);

    // ---- join V: ctx (bcv applied here; sum(attn)=1) --------------------------------
    cudaStreamWaitEvent(0, eV, 0);
    mma_gemm<64, 64, 32, 16, 256, true, true><<<dim3(1, 1, Hh * 32), blk, SMEM_TR(64)>>>(
        pattn, pvh2, fpart, Mm, Hh * 2 * Mm, Dd, Dd,
        2 * Mm, 64, 64, 32, sPsm, 1.0f, nullptr, 0, nullptr, nullptr, 0, 0);
    fin_sum_k<<<GRD(Bb * Dd), blk>>>(fpart, nullptr, pctx, Bb * Dd, Dd, 32, sPsm,
                                     fbcv, 0, nullptr, 0);

    // ---- ms --------------------------------------------------------------------------
    mma_gemm<64, 128, 32, 32, 256, true, false><<<dim3(8, 1, 16), blk, SMEM_TN(64, 128)>>>(
        pctx, poutw, fpart, Dd, 2 * Dd, 2 * Dd, Dd, 0, 0, 0, 16, sPsm, 1.0f,
        nullptr, 0, nullptr, nullptr, 0, 0);
    fin_sum_k<<<GRD(Bb * Dd), blk>>>(fpart, fms, nullptr, Bb * Dd, Dd, 16, sPsm,
                                     outb, 0, nullptr, 0);

    // ---- gate path ----------------------------------------------------------------------
    concat_split2_k<<<GRD(Bb * 2 * Dd), blk>>>(x, fms, pgin);
    mma_gemm<64, 128, 32, 32, 256, true, false><<<dim3(8, 1, 16), blk, SMEM_TN(64, 128)>>>(
        pgin, pgW1, fpart, 2 * Dd, 4 * Dd, 4 * Dd, Dd, 0, 0, 0, 16, sPsm, 1.0f,
        nullptr, 0, nullptr, nullptr, 0, 0);
    fin_sum_k<<<GRD(Bb * Dd), blk>>>(fpart, nullptr, pg1, Bb * Dd, Dd, 16, sPsm,
                                     gb1, 1, nullptr, 0);
    mma_gemm<64, 128, 32, 32, 256, true, false><<<dim3(8, 1, 16), blk, SMEM_TN(64, 128)>>>(
        pg1, pgW2, fpart, Dd, 2 * Dd, 2 * Dd, Dd, 0, 0, 0, 16, sPsm, 1.0f,
        nullptr, 0, nullptr, nullptr, 0, 0);
    fin_sum_k<<<GRD(Bb * Dd), blk>>>(fpart, fgated, nullptr, Bb * Dd, Dd, 16, sPsm,
                                     gb2, 2, fms, 0);

    // ---- output path ----------------------------------------------------------------------
    concat_split2_k<<<GRD(Bb * 2 * Dd), blk>>>(x, fgated, pcomb);
    mma_gemm<64, 128, 32, 32, 256, true, false><<<dim3(16, 1, 16), blk, SMEM_TN(64, 128)>>>(
        pcomb, piW1, fpart, 2 * Dd, 4 * Dd, 4 * Dd, 2 * Dd, 0, 0, 0, 16, sPi1, 1.0f,
        nullptr, 0, nullptr, nullptr, 0, 0);
    fin_sum_k<<<GRD(Bb * 2 * Dd), blk>>>(fpart, nullptr, pi1, Bb * 2 * Dd, 2 * Dd, 16, sPi1,
                                         ib1, 1, nullptr, 0);
    mma_gemm<64, 128, 32, 32, 256, true, false><<<dim3(8, 1, 16), blk, SMEM_TN(64, 128)>>>(
        pi1, piW2, fpart, 2 * Dd, 4 * Dd, 4 * Dd, Dd, 0, 0, 0, 16, sPsm, 1.0f,
        nullptr, 0, nullptr, nullptr, 0, 0);
    fin_sum_k<<<GRD(Bb * Dd), blk>>>(fpart, out, nullptr, Bb * Dd, Dd, 16, sPsm,
                                     ib2, 0, nullptr, 0);
}